// round 15
// baseline (speedup 1.0000x reference)
#include <cuda_runtime.h>
#include <cuda_fp16.h>
#include <math.h>

#define N_NODES   65536
#define E_EDGES   2097152
#define FEAT_IN   16
#define HID       32
#define N_GRAPHS  16
#define K_FC      131072      // 4096 * 32
#define FC_HID    256
#define LATENT    64
#define TILE_K    256
#define SLOTS     96          // bucket capacity per node; P(Poisson(32) > 96) ~ 1e-18

// Packed fp32x2 FMA (sm_103a FFMA2) — only reachable via PTX fma.rn.f32x2.
#define FMA_F32X2(d, a, b, c) \
    asm("fma.rn.f32x2 %0, %1, %2, %3;" : "=l"(d) : "l"(a), "l"(b), "l"(c))

// -------- scratch (static device globals; no runtime allocation) --------
__device__ float2 g_es[N_NODES * SLOTS];   // bucketed (src_bits, w); 48MB
__device__ int    g_cnt[N_NODES];          // zero-init; reset by fc1 each call
__device__ __half g_xh[N_NODES * FEAT_IN]; // fp16 copy of x (2MB)
__device__ __half g_hAh[N_NODES * HID];    // fp16 layer-1 output (4MB)
__device__ __half g_hBh[N_NODES * HID];    // fp16 layer-2 output (4MB)
__device__ float  g_hA[N_NODES * HID];     // fp32 layer-3 output (for FC1)
__device__ float  g_fc1[N_GRAPHS * FC_HID]; // zeroed by fill_kernel each call

__device__ __forceinline__ float elu(float v) {
    return v > 0.0f ? v : expm1f(v);
}

// Per-block dtype self-detection: if buffer is int64, hi-words of the first 32
// entries are all zero (indices < 65536); for int32 data they're random indices.
__device__ __forceinline__ int block_detect_is64(const unsigned int* ei32, int* s_is64) {
    if (threadIdx.x < 32) {
        unsigned int hi = ei32[threadIdx.x * 2 + 1];
        unsigned int ball = __ballot_sync(0xffffffffu, hi != 0u);
        if (threadIdx.x == 0) *s_is64 = (ball == 0u) ? 1 : 0;
    }
    __syncthreads();
    return *s_is64;
}

// -------- single-pass bucket fill (1 edge/thread) + x->fp16 + g_fc1 reset --------
__global__ __launch_bounds__(256)
void fill_kernel(const unsigned int* __restrict__ ei32, const float* __restrict__ w,
                 const float* __restrict__ x) {
    __shared__ int s_is64;
    int is64 = block_detect_is64(ei32, &s_is64);
    if (blockIdx.x == 0) {
        for (int i = threadIdx.x; i < N_GRAPHS * FC_HID; i += 256) g_fc1[i] = 0.0f;
    }
    long long e = (long long)blockIdx.x * 256 + threadIdx.x;
    // x -> half: first 4096 blocks convert exactly N*16 elements
    if (e < (long long)N_NODES * FEAT_IN) g_xh[e] = __float2half(x[e]);

    int s = is64 ? (int)ei32[2 * e]             : (int)ei32[e];
    int d = is64 ? (int)ei32[2 * (E_EDGES + e)] : (int)ei32[E_EDGES + e];
    float wv = w[e];
    int p = atomicAdd(&g_cnt[d], 1);
    if (p < SLOTS) g_es[d * SLOTS + p] = make_float2(__int_as_float(s), wv);
}

// HFMA2 a uint4 of 8 fp16 values into 4 half2 accumulators.
__device__ __forceinline__ void h8_hfma2(__half2* acch, uint4 v, __half2 w2) {
    acch[0] = __hfma2(*reinterpret_cast<__half2*>(&v.x), w2, acch[0]);
    acch[1] = __hfma2(*reinterpret_cast<__half2*>(&v.y), w2, acch[1]);
    acch[2] = __hfma2(*reinterpret_cast<__half2*>(&v.z), w2, acch[2]);
    acch[3] = __hfma2(*reinterpret_cast<__half2*>(&v.w), w2, acch[3]);
}

// -------- fused agg + linear + ELU, CIN=32: HFMA2 loop, fp32 epilogue --------
// c0 = lane&3 owns channels 8c0..8c0+7 (uint4 = 16B of a 64B fp16 row);
// g = lane>>2 owns one of 8 edge slots (each half2 acc sums only ~cnt/8 terms).
template <bool OUT_HALF>
__global__ __launch_bounds__(256)
void agg_linear32h_kernel(const __half* __restrict__ h,
                          const float* __restrict__ W,
                          const float* __restrict__ b,
                          __half* __restrict__ outh,
                          float* __restrict__ outf) {
    __shared__ float Ws[HID * HID];
    __shared__ float bs[HID];
    int tid = threadIdx.x;
    for (int i = tid; i < HID * HID; i += 256) Ws[i] = W[i];
    if (tid < HID) bs[tid] = b[tid];
    __syncthreads();

    int n = blockIdx.x * 8 + (tid >> 5);
    int lane = tid & 31;
    int c0 = lane & 3;
    int g = lane >> 2;
    int cnt = g_cnt[n];
    if (cnt > SLOTS) cnt = SLOTS;
    int e0 = n * SLOTS;
    int e1 = e0 + cnt;

    __half2 zero2 = __float2half2_rn(0.0f);
    __half2 acch[4] = {zero2, zero2, zero2, zero2};
    const uint4* h4 = (const uint4*)h;    // row n = h4[n*4 .. n*4+3]

    for (int base = e0; base < e1; base += 32) {
        float2 es[4];
#pragma unroll
        for (int j = 0; j < 4; j++) {
            int idx = base + 8 * j + g;
            es[j] = (idx < e1) ? __ldg(&g_es[idx]) : make_float2(0.0f, 0.0f);
        }
#pragma unroll
        for (int j = 0; j < 4; j++) {
            uint4 v = __ldg(&h4[__float_as_int(es[j].x) * 4 + c0]);
            h8_hfma2(acch, v, __float2half2_rn(es[j].y));
        }
    }

    // convert once per node: half2 accumulators -> fp32
    float acc[8];
#pragma unroll
    for (int i = 0; i < 4; i++) {
        float2 f = __half22float2(acch[i]);
        acc[2 * i]     = f.x;
        acc[2 * i + 1] = f.y;
    }

    // reduce over the 8 edge-slot groups (same c0: xor bits 2..4), fp32
#pragma unroll
    for (int off = 4; off <= 16; off <<= 1) {
#pragma unroll
        for (int i = 0; i < 8; i++)
            acc[i] += __shfl_xor_sync(0xffffffffu, acc[i], off);
    }

    // in-warp linear: agg channel k lives in acc[k&7] of lane (k>>3)
    float o = bs[lane];
#pragma unroll
    for (int k = 0; k < HID; k++) {
        float ak = __shfl_sync(0xffffffffu, acc[k & 7], k >> 3);
        o = fmaf(ak, Ws[k * HID + lane], o);
    }
    float r = elu(o);
    if (OUT_HALF) outh[n * HID + lane] = __float2half(r);
    else          outf[n * HID + lane] = r;
}

// -------- fused agg + linear + ELU, CIN=16: HFMA2 loop, fp32 epilogue --------
// c0 = lane&1 owns channels 8c0..8c0+7; g = lane>>1 owns one of 16 edge slots
// (each half2 acc sums only ~cnt/16 terms).
__global__ __launch_bounds__(256)
void agg_linear16h_kernel(const __half* __restrict__ xh,
                          const float* __restrict__ W,
                          const float* __restrict__ b,
                          __half* __restrict__ out) {
    __shared__ float Ws[FEAT_IN * HID];
    __shared__ float bs[HID];
    int tid = threadIdx.x;
    for (int i = tid; i < FEAT_IN * HID; i += 256) Ws[i] = W[i];
    if (tid < HID) bs[tid] = b[tid];
    __syncthreads();

    int n = blockIdx.x * 8 + (tid >> 5);
    int lane = tid & 31;
    int c0 = lane & 1;
    int g = lane >> 1;
    int cnt = g_cnt[n];
    if (cnt > SLOTS) cnt = SLOTS;
    int e0 = n * SLOTS;
    int e1 = e0 + cnt;

    __half2 zero2 = __float2half2_rn(0.0f);
    __half2 acch[4] = {zero2, zero2, zero2, zero2};
    const uint4* x4 = (const uint4*)xh;   // row n = x4[n*2 .. n*2+1]

    for (int base = e0; base < e1; base += 32) {
        float2 es[2];
#pragma unroll
        for (int j = 0; j < 2; j++) {
            int idx = base + 16 * j + g;
            es[j] = (idx < e1) ? __ldg(&g_es[idx]) : make_float2(0.0f, 0.0f);
        }
#pragma unroll
        for (int j = 0; j < 2; j++) {
            uint4 v = __ldg(&x4[__float_as_int(es[j].x) * 2 + c0]);
            h8_hfma2(acch, v, __float2half2_rn(es[j].y));
        }
    }

    float acc[8];
#pragma unroll
    for (int i = 0; i < 4; i++) {
        float2 f = __half22float2(acch[i]);
        acc[2 * i]     = f.x;
        acc[2 * i + 1] = f.y;
    }

    // reduce over the 16 edge-slot groups (same c0: xor bits 1..4)
#pragma unroll
    for (int off = 2; off <= 16; off <<= 1) {
#pragma unroll
        for (int i = 0; i < 8; i++)
            acc[i] += __shfl_xor_sync(0xffffffffu, acc[i], off);
    }

    // in-warp linear: agg channel k (0..15) lives in acc[k&7] of lane (k>>3)
    float o = bs[lane];
#pragma unroll
    for (int k = 0; k < FEAT_IN; k++) {
        float ak = __shfl_sync(0xffffffffu, acc[k & 7], k >> 3);
        o = fmaf(ak, Ws[k * HID + lane], o);
    }
    out[n * HID + lane] = __float2half(elu(o));
}

// -------- FC1 with packed f32x2 FMA: g_fc1 += H @ Wfc1; resets g_cnt --------
__global__ __launch_bounds__(256)
void fc1_kernel(const float* __restrict__ H, const float* __restrict__ Wfc1) {
    // reset bucket counters for the next graph replay (512 blocks * 256 >= N)
    int gid = blockIdx.x * 256 + threadIdx.x;
    if (gid < N_NODES) g_cnt[gid] = 0;

    __shared__ float Hs[TILE_K * N_GRAPHS];   // [k][m] layout, 16 KB
    int tid = threadIdx.x;
    int k0 = blockIdx.x * TILE_K;

    for (int i = tid; i < TILE_K * N_GRAPHS; i += 256) {
        int m = i / TILE_K;
        int k = i - m * TILE_K;
        Hs[k * N_GRAPHS + m] = H[m * K_FC + k0 + k];   // coalesced global read
    }
    __syncthreads();

    unsigned long long acc2[8];
#pragma unroll
    for (int i = 0; i < 8; i++) acc2[i] = 0ULL;

    for (int k = 0; k < TILE_K; k++) {
        float wv = __ldg(&Wfc1[(k0 + k) * FC_HID + tid]);     // coalesced
        unsigned long long wv2;
        unsigned int wu = __float_as_uint(wv);
        asm("mov.b64 %0, {%1, %2};" : "=l"(wv2) : "r"(wu), "r"(wu));
        const ulonglong2* hp = (const ulonglong2*)&Hs[k * N_GRAPHS];
        ulonglong2 p0 = hp[0], p1 = hp[1], p2 = hp[2], p3 = hp[3];
        FMA_F32X2(acc2[0], p0.x, wv2, acc2[0]);
        FMA_F32X2(acc2[1], p0.y, wv2, acc2[1]);
        FMA_F32X2(acc2[2], p1.x, wv2, acc2[2]);
        FMA_F32X2(acc2[3], p1.y, wv2, acc2[3]);
        FMA_F32X2(acc2[4], p2.x, wv2, acc2[4]);
        FMA_F32X2(acc2[5], p2.y, wv2, acc2[5]);
        FMA_F32X2(acc2[6], p3.x, wv2, acc2[6]);
        FMA_F32X2(acc2[7], p3.y, wv2, acc2[7]);
    }
#pragma unroll
    for (int i = 0; i < 8; i++) {
        unsigned int lo, hi;
        asm("mov.b64 {%0, %1}, %2;" : "=r"(lo), "=r"(hi) : "l"(acc2[i]));
        atomicAdd(&g_fc1[(2 * i)     * FC_HID + tid], __uint_as_float(lo));
        atomicAdd(&g_fc1[(2 * i + 1) * FC_HID + tid], __uint_as_float(hi));
    }
}

// -------- FC2: out[16,64] = elu(g_fc1 + bfc1) @ Wfc2 + bfc2 --------
__global__ __launch_bounds__(1024)
void fc2_kernel(const float* __restrict__ bfc1,
                const float* __restrict__ Wfc2,
                const float* __restrict__ bfc2,
                float* __restrict__ out) {
    __shared__ float s[N_GRAPHS * FC_HID];   // 16 KB
    int tid = threadIdx.x;
    for (int i = tid; i < N_GRAPHS * FC_HID; i += 1024) {
        float v = g_fc1[i] + bfc1[i & (FC_HID - 1)];
        s[i] = elu(v);
    }
    __syncthreads();

    int m = tid >> 6;
    int j = tid & 63;
    float acc = bfc2[j];
#pragma unroll 8
    for (int k = 0; k < FC_HID; k++)
        acc = fmaf(s[m * FC_HID + k], __ldg(&Wfc2[k * LATENT + j]), acc);
    out[m * LATENT + j] = acc;
}

extern "C" void kernel_launch(void* const* d_in, const int* in_sizes, int n_in,
                              void* d_out, int out_size) {
    // ---- size-based input mapping (ordering-agnostic) ----
    const float *x = 0, *ea = 0, *W1 = 0, *Wfc1 = 0, *bfc1 = 0, *Wfc2 = 0, *bfc2 = 0;
    const float *Wh[2] = {0, 0};       // W2, W3 (both 1024 elems, relative order kept)
    const float *bh[3] = {0, 0, 0};    // b1, b2, b3 (all 32 elems, relative order kept)
    const void  *ei = 0;
    int nWh = 0, nbh = 0;
    for (int i = 0; i < n_in; i++) {
        switch (in_sizes[i]) {
            case 1048576:  x    = (const float*)d_in[i]; break;  // 65536*16
            case 2097152:  ea   = (const float*)d_in[i]; break;  // E
            case 512:      W1   = (const float*)d_in[i]; break;  // 16*32
            case 1024:     if (nWh < 2) Wh[nWh++] = (const float*)d_in[i]; break;
            case 32:       if (nbh < 3) bh[nbh++] = (const float*)d_in[i]; break;
            case 33554432: Wfc1 = (const float*)d_in[i]; break;  // 131072*256
            case 256:      bfc1 = (const float*)d_in[i]; break;
            case 16384:    Wfc2 = (const float*)d_in[i]; break;  // 256*64
            case 64:       bfc2 = (const float*)d_in[i]; break;
            case 4194304:  ei   = d_in[i]; break;                // 2*E
            default: break;
        }
    }
    const float *W2 = Wh[0], *W3 = Wh[1];
    const float *b1 = bh[0], *b2 = bh[1], *b3 = bh[2];
    float* out = (float*)d_out;

    void *xhp, *hAhp, *hBhp, *hAp;
    cudaGetSymbolAddress(&xhp, g_xh);
    cudaGetSymbolAddress(&hAhp, g_hAh);
    cudaGetSymbolAddress(&hBhp, g_hBh);
    cudaGetSymbolAddress(&hAp, g_hA);

    // ---- single-pass bucket CSR + x->fp16; g_cnt reset by fc1 ----
    fill_kernel<<<E_EDGES / 256, 256>>>((const unsigned int*)ei, ea, x);   // 1

    // ---- layer 1: xh[N,16] -> hAh[N,32] (fp16) ----
    agg_linear16h_kernel<<<N_NODES / 8, 256>>>((const __half*)xhp, W1, b1,
                                               (__half*)hAhp);             // 2
    // ---- layer 2: hAh -> hBh (fp16) ----
    agg_linear32h_kernel<true><<<N_NODES / 8, 256>>>((const __half*)hAhp, W2, b2,
                                                     (__half*)hBhp, 0);    // 3
    // ---- layer 3: hBh -> hA (fp32, for FC1) ----  (4th launch — profiled)
    agg_linear32h_kernel<false><<<N_NODES / 8, 256>>>((const __half*)hBhp, W3, b3,
                                                      0, (float*)hAp);     // 4

    // ---- FC1 (g_fc1 pre-zeroed by fill; resets g_cnt) ----
    fc1_kernel<<<K_FC / TILE_K, 256>>>((const float*)hAp, Wfc1);           // 5

    // ---- FC2 -> output ----
    fc2_kernel<<<1, 1024>>>(bfc1, Wfc2, bfc2, out);                        // 6
}

// round 16
// speedup vs baseline: 1.0319x; 1.0319x over previous
#include <cuda_runtime.h>
#include <cuda_fp16.h>
#include <math.h>

#define N_NODES   65536
#define E_EDGES   2097152
#define FEAT_IN   16
#define HID       32
#define N_GRAPHS  16
#define K_FC      131072      // 4096 * 32
#define FC_HID    256
#define LATENT    64
#define TILE_K    256
#define SLOTS     96          // bucket capacity per node; P(Poisson(32) > 96) ~ 1e-18
#define NODES_PER_BLOCK 64    // 8 warps x 8 sequential nodes; W staged once per 64 nodes

// Packed fp32x2 FMA (sm_103a FFMA2) — only reachable via PTX fma.rn.f32x2.
#define FMA_F32X2(d, a, b, c) \
    asm("fma.rn.f32x2 %0, %1, %2, %3;" : "=l"(d) : "l"(a), "l"(b), "l"(c))

// -------- scratch (static device globals; no runtime allocation) --------
__device__ float2 g_es[N_NODES * SLOTS];   // bucketed (src_bits, w); 48MB
__device__ int    g_cnt[N_NODES];          // zero-init; reset by fc1 each call
__device__ __half g_xh[N_NODES * FEAT_IN]; // fp16 copy of x (2MB)
__device__ __half g_hAh[N_NODES * HID];    // fp16 layer-1 output (4MB)
__device__ __half g_hBh[N_NODES * HID];    // fp16 layer-2 output (4MB)
__device__ float  g_hA[N_NODES * HID];     // fp32 layer-3 output (for FC1)
__device__ float  g_fc1[N_GRAPHS * FC_HID]; // zeroed by fill_kernel each call

__device__ __forceinline__ float elu(float v) {
    return v > 0.0f ? v : expm1f(v);
}

// Per-block dtype self-detection: if buffer is int64, hi-words of the first 32
// entries are all zero (indices < 65536); for int32 data they're random indices.
__device__ __forceinline__ int block_detect_is64(const unsigned int* ei32, int* s_is64) {
    if (threadIdx.x < 32) {
        unsigned int hi = ei32[threadIdx.x * 2 + 1];
        unsigned int ball = __ballot_sync(0xffffffffu, hi != 0u);
        if (threadIdx.x == 0) *s_is64 = (ball == 0u) ? 1 : 0;
    }
    __syncthreads();
    return *s_is64;
}

// -------- single-pass bucket fill (1 edge/thread) + x->fp16 + g_fc1 reset --------
__global__ __launch_bounds__(256)
void fill_kernel(const unsigned int* __restrict__ ei32, const float* __restrict__ w,
                 const float* __restrict__ x) {
    __shared__ int s_is64;
    int is64 = block_detect_is64(ei32, &s_is64);
    if (blockIdx.x == 0) {
        for (int i = threadIdx.x; i < N_GRAPHS * FC_HID; i += 256) g_fc1[i] = 0.0f;
    }
    long long e = (long long)blockIdx.x * 256 + threadIdx.x;
    // x -> half: first 4096 blocks convert exactly N*16 elements
    if (e < (long long)N_NODES * FEAT_IN) g_xh[e] = __float2half(x[e]);

    int s = is64 ? (int)ei32[2 * e]             : (int)ei32[e];
    int d = is64 ? (int)ei32[2 * (E_EDGES + e)] : (int)ei32[E_EDGES + e];
    float wv = w[e];
    int p = atomicAdd(&g_cnt[d], 1);
    if (p < SLOTS) g_es[d * SLOTS + p] = make_float2(__int_as_float(s), wv);
}

// HFMA2 a uint4 of 8 fp16 values into 4 half2 accumulators.
__device__ __forceinline__ void h8_hfma2(__half2* acch, uint4 v, __half2 w2) {
    acch[0] = __hfma2(*reinterpret_cast<__half2*>(&v.x), w2, acch[0]);
    acch[1] = __hfma2(*reinterpret_cast<__half2*>(&v.y), w2, acch[1]);
    acch[2] = __hfma2(*reinterpret_cast<__half2*>(&v.z), w2, acch[2]);
    acch[3] = __hfma2(*reinterpret_cast<__half2*>(&v.w), w2, acch[3]);
}

// shfl_xor a half2 (as uint) and HADD2 into the accumulator
__device__ __forceinline__ __half2 h2_shfl_xor_add(__half2 a, int off) {
    unsigned int u = *reinterpret_cast<unsigned int*>(&a);
    unsigned int t = __shfl_xor_sync(0xffffffffu, u, off);
    return __hadd2(a, *reinterpret_cast<__half2*>(&t));
}

// -------- fused agg + linear + ELU, CIN=32: 64 nodes/block, HFMA2 loop --------
// c0 = lane&3 owns channels 8c0..8c0+7 (uint4 = 16B of a 64B fp16 row);
// g = lane>>2 owns one of 8 edge slots. Each warp processes 8 sequential nodes.
template <bool OUT_HALF>
__global__ __launch_bounds__(256)
void agg_linear32h_kernel(const __half* __restrict__ h,
                          const float* __restrict__ W,
                          const float* __restrict__ b,
                          __half* __restrict__ outh,
                          float* __restrict__ outf) {
    __shared__ float Ws[HID * HID];
    __shared__ float bs[HID];
    int tid = threadIdx.x;
    for (int i = tid; i < HID * HID; i += 256) Ws[i] = W[i];
    if (tid < HID) bs[tid] = b[tid];
    __syncthreads();

    int lane = tid & 31;
    int wid = tid >> 5;
    int c0 = lane & 3;
    int g = lane >> 2;
    const uint4* h4 = (const uint4*)h;    // row n = h4[n*4 .. n*4+3]
    float blane = bs[lane];

#pragma unroll 2
    for (int nn = 0; nn < 8; nn++) {
        int n = blockIdx.x * NODES_PER_BLOCK + wid * 8 + nn;
        int cnt = g_cnt[n];
        if (cnt > SLOTS) cnt = SLOTS;
        int e0 = n * SLOTS;
        int e1 = e0 + cnt;

        __half2 zero2 = __float2half2_rn(0.0f);
        __half2 acch[4] = {zero2, zero2, zero2, zero2};

        for (int base = e0; base < e1; base += 32) {
            float2 es[4];
#pragma unroll
            for (int j = 0; j < 4; j++) {
                int idx = base + 8 * j + g;
                es[j] = (idx < e1) ? __ldg(&g_es[idx]) : make_float2(0.0f, 0.0f);
            }
#pragma unroll
            for (int j = 0; j < 4; j++) {
                uint4 v = __ldg(&h4[__float_as_int(es[j].x) * 4 + c0]);
                h8_hfma2(acch, v, __float2half2_rn(es[j].y));
            }
        }

        // reduce over the 8 edge-slot groups in half2 (same c0: xor bits 2..4)
#pragma unroll
        for (int off = 4; off <= 16; off <<= 1) {
#pragma unroll
            for (int i = 0; i < 4; i++)
                acch[i] = h2_shfl_xor_add(acch[i], off);
        }

        // convert once per node: half2 accumulators -> fp32
        float acc[8];
#pragma unroll
        for (int i = 0; i < 4; i++) {
            float2 f = __half22float2(acch[i]);
            acc[2 * i]     = f.x;
            acc[2 * i + 1] = f.y;
        }

        // in-warp linear: agg channel k lives in acc[k&7] of lane (k>>3)
        float o = blane;
#pragma unroll
        for (int k = 0; k < HID; k++) {
            float ak = __shfl_sync(0xffffffffu, acc[k & 7], k >> 3);
            o = fmaf(ak, Ws[k * HID + lane], o);
        }
        float r = elu(o);
        if (OUT_HALF) outh[n * HID + lane] = __float2half(r);
        else          outf[n * HID + lane] = r;
    }
}

// -------- fused agg + linear + ELU, CIN=16: 64 nodes/block, HFMA2 loop --------
// c0 = lane&1 owns channels 8c0..8c0+7; g = lane>>1 owns one of 16 edge slots.
__global__ __launch_bounds__(256)
void agg_linear16h_kernel(const __half* __restrict__ xh,
                          const float* __restrict__ W,
                          const float* __restrict__ b,
                          __half* __restrict__ out) {
    __shared__ float Ws[FEAT_IN * HID];
    __shared__ float bs[HID];
    int tid = threadIdx.x;
    for (int i = tid; i < FEAT_IN * HID; i += 256) Ws[i] = W[i];
    if (tid < HID) bs[tid] = b[tid];
    __syncthreads();

    int lane = tid & 31;
    int wid = tid >> 5;
    int c0 = lane & 1;
    int g = lane >> 1;
    const uint4* x4 = (const uint4*)xh;   // row n = x4[n*2 .. n*2+1]
    float blane = bs[lane];

#pragma unroll 2
    for (int nn = 0; nn < 8; nn++) {
        int n = blockIdx.x * NODES_PER_BLOCK + wid * 8 + nn;
        int cnt = g_cnt[n];
        if (cnt > SLOTS) cnt = SLOTS;
        int e0 = n * SLOTS;
        int e1 = e0 + cnt;

        __half2 zero2 = __float2half2_rn(0.0f);
        __half2 acch[4] = {zero2, zero2, zero2, zero2};

        for (int base = e0; base < e1; base += 32) {
            float2 es[2];
#pragma unroll
            for (int j = 0; j < 2; j++) {
                int idx = base + 16 * j + g;
                es[j] = (idx < e1) ? __ldg(&g_es[idx]) : make_float2(0.0f, 0.0f);
            }
#pragma unroll
            for (int j = 0; j < 2; j++) {
                uint4 v = __ldg(&x4[__float_as_int(es[j].x) * 2 + c0]);
                h8_hfma2(acch, v, __float2half2_rn(es[j].y));
            }
        }

        // reduce over the 16 edge-slot groups in half2 (same c0: xor bits 1..4)
#pragma unroll
        for (int off = 2; off <= 16; off <<= 1) {
#pragma unroll
            for (int i = 0; i < 4; i++)
                acch[i] = h2_shfl_xor_add(acch[i], off);
        }

        float acc[8];
#pragma unroll
        for (int i = 0; i < 4; i++) {
            float2 f = __half22float2(acch[i]);
            acc[2 * i]     = f.x;
            acc[2 * i + 1] = f.y;
        }

        // in-warp linear: agg channel k (0..15) lives in acc[k&7] of lane (k>>3)
        float o = blane;
#pragma unroll
        for (int k = 0; k < FEAT_IN; k++) {
            float ak = __shfl_sync(0xffffffffu, acc[k & 7], k >> 3);
            o = fmaf(ak, Ws[k * HID + lane], o);
        }
        out[n * HID + lane] = __float2half(elu(o));
    }
}

// -------- FC1 with packed f32x2 FMA: g_fc1 += H @ Wfc1; resets g_cnt --------
__global__ __launch_bounds__(256)
void fc1_kernel(const float* __restrict__ H, const float* __restrict__ Wfc1) {
    // reset bucket counters for the next graph replay (512 blocks * 256 >= N)
    int gid = blockIdx.x * 256 + threadIdx.x;
    if (gid < N_NODES) g_cnt[gid] = 0;

    __shared__ float Hs[TILE_K * N_GRAPHS];   // [k][m] layout, 16 KB
    int tid = threadIdx.x;
    int k0 = blockIdx.x * TILE_K;

    for (int i = tid; i < TILE_K * N_GRAPHS; i += 256) {
        int m = i / TILE_K;
        int k = i - m * TILE_K;
        Hs[k * N_GRAPHS + m] = H[m * K_FC + k0 + k];   // coalesced global read
    }
    __syncthreads();

    unsigned long long acc2[8];
#pragma unroll
    for (int i = 0; i < 8; i++) acc2[i] = 0ULL;

    for (int k = 0; k < TILE_K; k++) {
        float wv = __ldg(&Wfc1[(k0 + k) * FC_HID + tid]);     // coalesced
        unsigned long long wv2;
        unsigned int wu = __float_as_uint(wv);
        asm("mov.b64 %0, {%1, %2};" : "=l"(wv2) : "r"(wu), "r"(wu));
        const ulonglong2* hp = (const ulonglong2*)&Hs[k * N_GRAPHS];
        ulonglong2 p0 = hp[0], p1 = hp[1], p2 = hp[2], p3 = hp[3];
        FMA_F32X2(acc2[0], p0.x, wv2, acc2[0]);
        FMA_F32X2(acc2[1], p0.y, wv2, acc2[1]);
        FMA_F32X2(acc2[2], p1.x, wv2, acc2[2]);
        FMA_F32X2(acc2[3], p1.y, wv2, acc2[3]);
        FMA_F32X2(acc2[4], p2.x, wv2, acc2[4]);
        FMA_F32X2(acc2[5], p2.y, wv2, acc2[5]);
        FMA_F32X2(acc2[6], p3.x, wv2, acc2[6]);
        FMA_F32X2(acc2[7], p3.y, wv2, acc2[7]);
    }
#pragma unroll
    for (int i = 0; i < 8; i++) {
        unsigned int lo, hi;
        asm("mov.b64 {%0, %1}, %2;" : "=r"(lo), "=r"(hi) : "l"(acc2[i]));
        atomicAdd(&g_fc1[(2 * i)     * FC_HID + tid], __uint_as_float(lo));
        atomicAdd(&g_fc1[(2 * i + 1) * FC_HID + tid], __uint_as_float(hi));
    }
}

// -------- FC2: out[16,64] = elu(g_fc1 + bfc1) @ Wfc2 + bfc2 --------
__global__ __launch_bounds__(1024)
void fc2_kernel(const float* __restrict__ bfc1,
                const float* __restrict__ Wfc2,
                const float* __restrict__ bfc2,
                float* __restrict__ out) {
    __shared__ float s[N_GRAPHS * FC_HID];   // 16 KB
    int tid = threadIdx.x;
    for (int i = tid; i < N_GRAPHS * FC_HID; i += 1024) {
        float v = g_fc1[i] + bfc1[i & (FC_HID - 1)];
        s[i] = elu(v);
    }
    __syncthreads();

    int m = tid >> 6;
    int j = tid & 63;
    float acc = bfc2[j];
#pragma unroll 8
    for (int k = 0; k < FC_HID; k++)
        acc = fmaf(s[m * FC_HID + k], __ldg(&Wfc2[k * LATENT + j]), acc);
    out[m * LATENT + j] = acc;
}

extern "C" void kernel_launch(void* const* d_in, const int* in_sizes, int n_in,
                              void* d_out, int out_size) {
    // ---- size-based input mapping (ordering-agnostic) ----
    const float *x = 0, *ea = 0, *W1 = 0, *Wfc1 = 0, *bfc1 = 0, *Wfc2 = 0, *bfc2 = 0;
    const float *Wh[2] = {0, 0};       // W2, W3 (both 1024 elems, relative order kept)
    const float *bh[3] = {0, 0, 0};    // b1, b2, b3 (all 32 elems, relative order kept)
    const void  *ei = 0;
    int nWh = 0, nbh = 0;
    for (int i = 0; i < n_in; i++) {
        switch (in_sizes[i]) {
            case 1048576:  x    = (const float*)d_in[i]; break;  // 65536*16
            case 2097152:  ea   = (const float*)d_in[i]; break;  // E
            case 512:      W1   = (const float*)d_in[i]; break;  // 16*32
            case 1024:     if (nWh < 2) Wh[nWh++] = (const float*)d_in[i]; break;
            case 32:       if (nbh < 3) bh[nbh++] = (const float*)d_in[i]; break;
            case 33554432: Wfc1 = (const float*)d_in[i]; break;  // 131072*256
            case 256:      bfc1 = (const float*)d_in[i]; break;
            case 16384:    Wfc2 = (const float*)d_in[i]; break;  // 256*64
            case 64:       bfc2 = (const float*)d_in[i]; break;
            case 4194304:  ei   = d_in[i]; break;                // 2*E
            default: break;
        }
    }
    const float *W2 = Wh[0], *W3 = Wh[1];
    const float *b1 = bh[0], *b2 = bh[1], *b3 = bh[2];
    float* out = (float*)d_out;

    void *xhp, *hAhp, *hBhp, *hAp;
    cudaGetSymbolAddress(&xhp, g_xh);
    cudaGetSymbolAddress(&hAhp, g_hAh);
    cudaGetSymbolAddress(&hBhp, g_hBh);
    cudaGetSymbolAddress(&hAp, g_hA);

    // ---- single-pass bucket CSR + x->fp16; g_cnt reset by fc1 ----
    fill_kernel<<<E_EDGES / 256, 256>>>((const unsigned int*)ei, ea, x);   // 1

    // ---- layer 1: xh[N,16] -> hAh[N,32] (fp16) ----
    agg_linear16h_kernel<<<N_NODES / NODES_PER_BLOCK, 256>>>(
        (const __half*)xhp, W1, b1, (__half*)hAhp);                        // 2
    // ---- layer 2: hAh -> hBh (fp16) ----
    agg_linear32h_kernel<true><<<N_NODES / NODES_PER_BLOCK, 256>>>(
        (const __half*)hAhp, W2, b2, (__half*)hBhp, 0);                    // 3
    // ---- layer 3: hBh -> hA (fp32, for FC1) ----  (4th launch — profiled)
    agg_linear32h_kernel<false><<<N_NODES / NODES_PER_BLOCK, 256>>>(
        (const __half*)hBhp, W3, b3, 0, (float*)hAp);                      // 4

    // ---- FC1 (g_fc1 pre-zeroed by fill; resets g_cnt) ----
    fc1_kernel<<<K_FC / TILE_K, 256>>>((const float*)hAp, Wfc1);           // 5

    // ---- FC2 -> output ----
    fc2_kernel<<<1, 1024>>>(bfc1, Wfc2, bfc2, out);                        // 6
}